// round 11
// baseline (speedup 1.0000x reference)
#include <cuda_runtime.h>
#include <cstdint>

// Problem constants
#define NBUCKETS 16
#define EMBD     1024
#define VOCAB    32000
#define SEQLEN   2048
#define RANK     8
#define BATCH    2
#define NTOK     (BATCH * SEQLEN)          // 4096 tokens
#define BUCKET_SHIFT 7                      // SEQLEN / NBUCKETS = 128 = 1<<7

// Scratch for the low-rank projection (alpha folded in): [NTOK][RANK]
__device__ float g_low[NTOK * RANK];

// ---------------------------------------------------------------------------
// Kernel 1 (v5): low[bt][r] = alpha * sum_e hidden[bt][e] * A[bucket(t)][e][r]
//
// 256 CTAs x 16 tokens, 2 CTAs/SM. E is split across warp halves:
// warps 0-3 cover e in [0,512), warps 4-7 cover [512,1024). Each warp then
// processes 4 tokens over only 4 k-iters, halving per-thread LDS vs v4
// (32 LDS.128 instead of 64) while keeping full amortization of shared A
// reads over 4 tokens. Partials from the two halves combine through a 1KB
// smem buffer. Hidden loads are batched per k-iter for high MLP.
// ---------------------------------------------------------------------------
#define K1_TOKS 16
#define K1_TPB  256
#define TPW     4            // tokens per warp
#define EHALF   512
#define KITERS  (EHALF / 128)   // 4

__global__ __launch_bounds__(K1_TPB, 2)
void lowproj_kernel(const float* __restrict__ hidden,
                    const float* __restrict__ A,
                    const float* __restrict__ alpha_p)
{
    __shared__ float sAT[RANK][EMBD];             // 32 KB transposed A bucket
    __shared__ float part[2][K1_TOKS][RANK];      // 1 KB cross-half partials

    const int tok0   = blockIdx.x * K1_TOKS;
    const int bucket = (tok0 & (SEQLEN - 1)) >> BUCKET_SHIFT;
    const float* __restrict__ Ab = A + (size_t)bucket * EMBD * RANK;

    // Cooperative load + transpose: 2048 float4, 8 per thread.
    for (int i = threadIdx.x; i < EMBD * RANK / 4; i += K1_TPB) {
        float4 v = reinterpret_cast<const float4*>(Ab)[i];
        const int e = i >> 1;
        const int q = (i & 1) * 4;
        sAT[q + 0][e] = v.x;
        sAT[q + 1][e] = v.y;
        sAT[q + 2][e] = v.z;
        sAT[q + 3][e] = v.w;
    }
    __syncthreads();

    const int wid  = threadIdx.x >> 5;
    const int lane = threadIdx.x & 31;
    const int half = wid >> 2;                    // e-half: 0 or 1
    const int wg   = wid & 3;                     // token-group within half
    const int wtok = tok0 + wg * TPW;             // this warp's 4 tokens
    const float* __restrict__ h0 = hidden + (size_t)wtok * EMBD + half * EHALF;

    // acc index i = g*8 + r  (g = token-in-warp 0..3, r = rank)
    float v[TPW * RANK];
#pragma unroll
    for (int i = 0; i < TPW * RANK; i++) v[i] = 0.0f;

#pragma unroll
    for (int k = 0; k < KITERS; k++) {
        const int eo = k * 128 + lane * 4;        // offset within this half
        float4 hv[TPW];
#pragma unroll
        for (int g = 0; g < TPW; g++)
            hv[g] = __ldcs(reinterpret_cast<const float4*>(h0 + (size_t)g * EMBD + eo));
        const int e = half * EHALF + eo;          // index into sAT
#pragma unroll
        for (int r = 0; r < RANK; r++) {
            const float4 av = *reinterpret_cast<const float4*>(&sAT[r][e]);
#pragma unroll
            for (int g = 0; g < TPW; g++) {
                v[g * RANK + r] = fmaf(hv[g].x, av.x,
                                  fmaf(hv[g].y, av.y,
                                  fmaf(hv[g].z, av.z,
                                  fmaf(hv[g].w, av.w, v[g * RANK + r]))));
            }
        }
    }

    // Split-butterfly reduce: 32 values over 32 lanes, 31 shuffles.
    // After: lane l holds the warp-sum for token g = l>>3, rank r = l&7.
#pragma unroll
    for (int m = 16; m >= 1; m >>= 1) {
        const bool hi = (lane & m) != 0;
        const int h = m;
#pragma unroll
        for (int j = 0; j < 16; j++) {
            if (j < h) {
                float mine   = hi ? v[h + j] : v[j];
                float theirs = hi ? v[j]     : v[h + j];
                v[j] = mine + __shfl_xor_sync(0xFFFFFFFFu, theirs, m);
            }
        }
    }

    // Per warp: 32 lanes write 32 consecutive floats (128B, conflict-free).
    part[half][wg * TPW + (lane >> 3)][lane & 7] = v[0];
    __syncthreads();

    // Combine halves, scale, store: 128 threads write 512B coalesced.
    if (threadIdx.x < K1_TOKS * RANK) {
        const int tok = threadIdx.x >> 3;
        const int r   = threadIdx.x & 7;
        g_low[(size_t)(tok0 + tok) * RANK + r] =
            (part[0][tok][r] + part[1][tok][r]) * alpha_p[0];
    }
}

// ---------------------------------------------------------------------------
// Kernel 2: out[bt][v] = sum_r low[bt][r] * B[r][v]
// (unchanged — pinned at the streaming-store path ceiling, ~6.1-6.2 TB/s)
// ---------------------------------------------------------------------------
#define T_TILE 64
#define K2_THREADS 256
#define V4 (VOCAB / 4)        // 8000 float4 per row

__global__ __launch_bounds__(K2_THREADS, 4)
void vocabproj_kernel(const float* __restrict__ B,
                      float* __restrict__ out)
{
    const int v4  = blockIdx.x * K2_THREADS + threadIdx.x;  // float4 column index
    const bool valid = (v4 < V4);
    const int v = v4 * 4;

    // Load B panel into registers: 8 rows x 4 cols
    float4 b[RANK];
#pragma unroll
    for (int r = 0; r < RANK; r++) {
        if (valid)
            b[r] = *reinterpret_cast<const float4*>(B + (size_t)r * VOCAB + v);
        else
            b[r] = make_float4(0.f, 0.f, 0.f, 0.f);
    }

    // Cooperative load of this block's token-tile of low into shared
    __shared__ float slow[T_TILE * RANK];    // 2 KB
    const int tok0 = blockIdx.y * T_TILE;
    for (int i = threadIdx.x; i < T_TILE * RANK / 4; i += K2_THREADS) {
        reinterpret_cast<float4*>(slow)[i] =
            reinterpret_cast<const float4*>(g_low + (size_t)tok0 * RANK)[i];
    }
    __syncthreads();

    if (!valid) return;

    float* __restrict__ op = out + (size_t)tok0 * VOCAB + v;

#pragma unroll 4
    for (int tt = 0; tt < T_TILE; tt++) {
        const float* l = slow + tt * RANK;   // broadcast shared reads
        float4 o;
        o.x = l[0] * b[0].x; o.y = l[0] * b[0].y; o.z = l[0] * b[0].z; o.w = l[0] * b[0].w;
#pragma unroll
        for (int r = 1; r < RANK; r++) {
            o.x = fmaf(l[r], b[r].x, o.x);
            o.y = fmaf(l[r], b[r].y, o.y);
            o.z = fmaf(l[r], b[r].z, o.z);
            o.w = fmaf(l[r], b[r].w, o.w);
        }
        __stcs(reinterpret_cast<float4*>(op), o);   // streaming store
        op += VOCAB;
    }
}

// ---------------------------------------------------------------------------
// Launch
// ---------------------------------------------------------------------------
extern "C" void kernel_launch(void* const* d_in, const int* in_sizes, int n_in,
                              void* d_out, int out_size)
{
    const float* hidden = (const float*)d_in[0];   // [2,2048,1024]
    const float* A      = (const float*)d_in[1];   // [16,1024,8]
    const float* B      = (const float*)d_in[2];   // [8,32000]
    const float* alpha  = (const float*)d_in[3];   // scalar
    float* out          = (float*)d_out;           // [2,2048,32000]

    lowproj_kernel<<<NTOK / K1_TOKS, K1_TPB>>>(hidden, A, alpha);

    dim3 grid2((V4 + K2_THREADS - 1) / K2_THREADS,   // 32
               NTOK / T_TILE);                       // 64
    vocabproj_kernel<<<grid2, K2_THREADS>>>(B, out);
}

// round 13
// speedup vs baseline: 1.0060x; 1.0060x over previous
#include <cuda_runtime.h>
#include <cstdint>

// Problem constants
#define NBUCKETS 16
#define EMBD     1024
#define VOCAB    32000
#define SEQLEN   2048
#define RANK     8
#define BATCH    2
#define NTOK     (BATCH * SEQLEN)          // 4096 tokens
#define BUCKET_SHIFT 7                      // SEQLEN / NBUCKETS = 128 = 1<<7

// Scratch for the low-rank projection (alpha folded in): [NTOK][RANK]
__device__ float g_low[NTOK * RANK];

// ---------------------------------------------------------------------------
// Kernel 1 (v6): low[bt][r] = alpha * sum_e hidden[bt][e] * A[bucket(t)][e][r]
//
// NO shared-memory A, no transpose, no prologue barrier. Thread t owns
// e = 4t..4t+3; the A values it needs (A[e][0..7], 32 floats) are loaded once
// into registers. Main loop is pure LDG(hidden)+FFMA. Each warp covers a
// 128-wide e-slice and produces partials for all 16 tokens of the tile in
// 4 butterfly groups of 4 tokens; the 8 warps' partials combine through a
// 4KB smem buffer with one __syncthreads.
// ---------------------------------------------------------------------------
#define K1_TOKS 16
#define K1_TPB  256
#define TGRP    4            // tokens per butterfly group

__global__ __launch_bounds__(K1_TPB, 2)
void lowproj_kernel(const float* __restrict__ hidden,
                    const float* __restrict__ A,
                    const float* __restrict__ alpha_p)
{
    __shared__ float part[8][K1_TOKS][RANK];      // 4 KB warp partials

    const int tok0   = blockIdx.x * K1_TOKS;
    const int bucket = (tok0 & (SEQLEN - 1)) >> BUCKET_SHIFT;
    const float* __restrict__ Ab = A + (size_t)bucket * EMBD * RANK;

    const int tid  = threadIdx.x;
    const int wid  = tid >> 5;
    const int lane = tid & 31;
    const int e0   = tid * 4;                     // thread's 4 e-values

    // A panel in registers: a[k*2], a[k*2+1] = A[e0+k][0..3], A[e0+k][4..7]
    float4 a[8];
#pragma unroll
    for (int j = 0; j < 8; j++)
        a[j] = *reinterpret_cast<const float4*>(Ab + (size_t)e0 * RANK + j * 4);
    const float* af = reinterpret_cast<const float*>(a);  // af[k*8+r]

    const float* __restrict__ hbase = hidden + (size_t)tok0 * EMBD + e0;

#pragma unroll
    for (int grp = 0; grp < K1_TOKS / TGRP; grp++) {
        // Batched hidden loads for 4 tokens (high MLP, coalesced 512B/warp).
        float4 hv[TGRP];
#pragma unroll
        for (int g = 0; g < TGRP; g++)
            hv[g] = __ldcs(reinterpret_cast<const float4*>(
                        hbase + (size_t)(grp * TGRP + g) * EMBD));
        const float* hf = reinterpret_cast<const float*>(hv); // hf[g*4+k]

        // acc index i = g*8 + r
        float v[TGRP * RANK];
#pragma unroll
        for (int i = 0; i < TGRP * RANK; i++) v[i] = 0.0f;

#pragma unroll
        for (int k = 0; k < 4; k++) {
#pragma unroll
            for (int r = 0; r < RANK; r++) {
                const float av = af[k * RANK + r];
#pragma unroll
                for (int g = 0; g < TGRP; g++)
                    v[g * RANK + r] = fmaf(hf[g * 4 + k], av, v[g * RANK + r]);
            }
        }

        // Split-butterfly: 32 values over 32 lanes, 31 shuffles.
        // After: lane l holds the warp-sum for g = l>>3, r = l&7.
#pragma unroll
        for (int m = 16; m >= 1; m >>= 1) {
            const bool hi = (lane & m) != 0;
            const int h = m;
#pragma unroll
            for (int j = 0; j < 16; j++) {
                if (j < h) {
                    float mine   = hi ? v[h + j] : v[j];
                    float theirs = hi ? v[j]     : v[h + j];
                    v[j] = mine + __shfl_xor_sync(0xFFFFFFFFu, theirs, m);
                }
            }
        }

        // One conflict-free 128B line per warp.
        part[wid][grp * TGRP + (lane >> 3)][lane & 7] = v[0];
    }
    __syncthreads();

    // Combine the 8 warps' e-slice partials; 128 threads store 512B coalesced.
    if (tid < K1_TOKS * RANK) {
        const int tok = tid >> 3;
        const int r   = tid & 7;
        float s = 0.0f;
#pragma unroll
        for (int w = 0; w < 8; w++) s += part[w][tok][r];
        g_low[(size_t)(tok0 + tok) * RANK + r] = s * alpha_p[0];
    }
}

// ---------------------------------------------------------------------------
// Kernel 2: out[bt][v] = sum_r low[bt][r] * B[r][v]
// (unchanged — pinned at the streaming-store path ceiling, ~6.1-6.2 TB/s)
// ---------------------------------------------------------------------------
#define T_TILE 64
#define K2_THREADS 256
#define V4 (VOCAB / 4)        // 8000 float4 per row

__global__ __launch_bounds__(K2_THREADS, 4)
void vocabproj_kernel(const float* __restrict__ B,
                      float* __restrict__ out)
{
    const int v4  = blockIdx.x * K2_THREADS + threadIdx.x;  // float4 column index
    const bool valid = (v4 < V4);
    const int v = v4 * 4;

    // Load B panel into registers: 8 rows x 4 cols
    float4 b[RANK];
#pragma unroll
    for (int r = 0; r < RANK; r++) {
        if (valid)
            b[r] = *reinterpret_cast<const float4*>(B + (size_t)r * VOCAB + v);
        else
            b[r] = make_float4(0.f, 0.f, 0.f, 0.f);
    }

    // Cooperative load of this block's token-tile of low into shared
    __shared__ float slow[T_TILE * RANK];    // 2 KB
    const int tok0 = blockIdx.y * T_TILE;
    for (int i = threadIdx.x; i < T_TILE * RANK / 4; i += K2_THREADS) {
        reinterpret_cast<float4*>(slow)[i] =
            reinterpret_cast<const float4*>(g_low + (size_t)tok0 * RANK)[i];
    }
    __syncthreads();

    if (!valid) return;

    float* __restrict__ op = out + (size_t)tok0 * VOCAB + v;

#pragma unroll 4
    for (int tt = 0; tt < T_TILE; tt++) {
        const float* l = slow + tt * RANK;   // broadcast shared reads
        float4 o;
        o.x = l[0] * b[0].x; o.y = l[0] * b[0].y; o.z = l[0] * b[0].z; o.w = l[0] * b[0].w;
#pragma unroll
        for (int r = 1; r < RANK; r++) {
            o.x = fmaf(l[r], b[r].x, o.x);
            o.y = fmaf(l[r], b[r].y, o.y);
            o.z = fmaf(l[r], b[r].z, o.z);
            o.w = fmaf(l[r], b[r].w, o.w);
        }
        __stcs(reinterpret_cast<float4*>(op), o);   // streaming store
        op += VOCAB;
    }
}

// ---------------------------------------------------------------------------
// Launch
// ---------------------------------------------------------------------------
extern "C" void kernel_launch(void* const* d_in, const int* in_sizes, int n_in,
                              void* d_out, int out_size)
{
    const float* hidden = (const float*)d_in[0];   // [2,2048,1024]
    const float* A      = (const float*)d_in[1];   // [16,1024,8]
    const float* B      = (const float*)d_in[2];   // [8,32000]
    const float* alpha  = (const float*)d_in[3];   // scalar
    float* out          = (float*)d_out;           // [2,2048,32000]

    lowproj_kernel<<<NTOK / K1_TOKS, K1_TPB>>>(hidden, A, alpha);

    dim3 grid2((V4 + K2_THREADS - 1) / K2_THREADS,   // 32
               NTOK / T_TILE);                       // 64
    vocabproj_kernel<<<grid2, K2_THREADS>>>(B, out);
}